// round 8
// baseline (speedup 1.0000x reference)
#include <cuda_runtime.h>
#include <cuda_bf16.h>
#include <stdint.h>

// ===========================================================================
// CavAttention via mma.sync bf16 hi/lo split precision (3 merged passes)
// Round 8: Round-7 structure with fixed buffer geometry (27 groups per CTA).
//   prep: wqkv/wout -> bf16 hi/lo global images (padded pitch 136)
//   K1:   qkv = xp @ wqkv                       (HMMA)  -> g_qkv
//   K23:  attention (softmax+PV) + out GEMM + bias + transposed store
// ===========================================================================

#define HW_   8448
#define NROWS 84480

__device__ __align__(16) float g_qkv[(size_t)NROWS * 768];
__device__ __align__(16) __nv_bfloat16 g_w1h[6 * 4 * 64 * 136];
__device__ __align__(16) __nv_bfloat16 g_w1l[6 * 4 * 64 * 136];
__device__ __align__(16) __nv_bfloat16 g_w2h[2 * 4 * 64 * 136];
__device__ __align__(16) __nv_bfloat16 g_w2l[2 * 4 * 64 * 136];

#define AP 264            // A smem pitch (bf16): 528B
#define BP 136            // B smem pitch (bf16): 272B

#define CHUNK_B  17408    // one 64x136 bf16 image (bytes)
#define BUF_B    (2 * CHUNK_B)

// ----------------------------- helpers ------------------------------------
__device__ __forceinline__ uint32_t smem_u32(const void* p) {
    uint32_t a;
    asm("{ .reg .u64 t; cvta.to.shared.u64 t, %1; cvt.u32.u64 %0, t; }" : "=r"(a) : "l"(p));
    return a;
}
__device__ __forceinline__ float bres(float f) {
    return f - __bfloat162float(__float2bfloat16(f));
}
__device__ __forceinline__ uint64_t pack4(float a0, float a1, float a2, float a3) {
    uint64_t r = (uint64_t)__bfloat16_as_ushort(__float2bfloat16(a0));
    r |= (uint64_t)__bfloat16_as_ushort(__float2bfloat16(a1)) << 16;
    r |= (uint64_t)__bfloat16_as_ushort(__float2bfloat16(a2)) << 32;
    r |= (uint64_t)__bfloat16_as_ushort(__float2bfloat16(a3)) << 48;
    return r;
}
__device__ __forceinline__ void cpa16(uint32_t dst, const void* src) {
    asm volatile("cp.async.cg.shared.global [%0], [%1], 16;" :: "r"(dst), "l"(src));
}
#define CP_COMMIT() asm volatile("cp.async.commit_group;" ::: "memory")
#define CP_WAIT(n)  asm volatile("cp.async.wait_group %0;" :: "n"(n) : "memory")

__device__ __forceinline__ void ldmA(uint32_t* r, uint32_t addr) {
    asm volatile("ldmatrix.sync.aligned.m8n8.x4.shared.b16 {%0,%1,%2,%3}, [%4];"
                 : "=r"(r[0]), "=r"(r[1]), "=r"(r[2]), "=r"(r[3]) : "r"(addr));
}
__device__ __forceinline__ void ldmB(uint32_t* r, uint32_t addr) {
    asm volatile("ldmatrix.sync.aligned.m8n8.x2.trans.shared.b16 {%0,%1}, [%2];"
                 : "=r"(r[0]), "=r"(r[1]) : "r"(addr));
}
__device__ __forceinline__ void mma16816(float* c, const uint32_t* a, const uint32_t* b) {
    asm volatile("mma.sync.aligned.m16n8k16.row.col.f32.bf16.bf16.f32 "
                 "{%0,%1,%2,%3}, {%4,%5,%6,%7}, {%8,%9}, {%0,%1,%2,%3};"
                 : "+f"(c[0]), "+f"(c[1]), "+f"(c[2]), "+f"(c[3])
                 : "r"(a[0]), "r"(a[1]), "r"(a[2]), "r"(a[3]), "r"(b[0]), "r"(b[1]));
}

// merged-pass, register-double-buffered 64-deep K chunk. acc = warp tile 64x32
#define LOADSTAGE(s, ks)                                                      \
    do {                                                                      \
        _Pragma("unroll")                                                     \
        for (int i_ = 0; i_ < 4; ++i_) {                                      \
            ldmA(ah[s][i_], aHi + (uint32_t)((i_ * 16 * AP + (ks) * 16) * 2));\
            ldmA(al[s][i_], aLo + (uint32_t)((i_ * 16 * AP + (ks) * 16) * 2));\
        }                                                                     \
        _Pragma("unroll")                                                     \
        for (int j_ = 0; j_ < 4; ++j_) {                                      \
            ldmB(bh[s][j_], bHi + (uint32_t)(((ks) * 16 * BP + j_ * 8) * 2)); \
            ldmB(bl[s][j_], bLo + (uint32_t)(((ks) * 16 * BP + j_ * 8) * 2)); \
        }                                                                     \
    } while (0)

__device__ __forceinline__ void mma_chunk(float acc[4][4][4],
                                          uint32_t aHi, uint32_t aLo,
                                          uint32_t bHi, uint32_t bLo) {
    uint32_t ah[2][4][4], al[2][4][4], bh[2][4][2], bl[2][4][2];
    LOADSTAGE(0, 0);
    #pragma unroll
    for (int ks = 0; ks < 4; ++ks) {
        const int cur = ks & 1, nxt = cur ^ 1;
        if (ks < 3) LOADSTAGE(nxt, ks + 1);
        #pragma unroll
        for (int i = 0; i < 4; ++i)
            #pragma unroll
            for (int j = 0; j < 4; ++j)
                mma16816(acc[i][j], ah[cur][i], bh[cur][j]);
        #pragma unroll
        for (int i = 0; i < 4; ++i)
            #pragma unroll
            for (int j = 0; j < 4; ++j)
                mma16816(acc[i][j], ah[cur][i], bl[cur][j]);
        #pragma unroll
        for (int i = 0; i < 4; ++i)
            #pragma unroll
            for (int j = 0; j < 4; ++j)
                mma16816(acc[i][j], al[cur][i], bh[cur][j]);
    }
}

// issue one B chunk (hi+lo) via cp.async; 1088 uint4 per image
__device__ __forceinline__ void stage_B(uint32_t dst, const __nv_bfloat16* srcH,
                                        const __nv_bfloat16* srcL, int tid) {
    const char* sH = (const char*)srcH;
    const char* sL = (const char*)srcL;
    #pragma unroll
    for (int q = 0; q < 5; ++q) {
        int e = tid + q * 256;
        if (e < 1088) {
            cpa16(dst + e * 16, sH + e * 16);
            cpa16(dst + CHUNK_B + e * 16, sL + e * 16);
        }
    }
    CP_COMMIT();
}

// ======================= prep: weight conversion ===========================
__global__ __launch_bounds__(256) void prep_w(const float* __restrict__ wqkv,
                                              const float* __restrict__ wout) {
    int idx = blockIdx.x * 256 + threadIdx.x;
    if (idx < 196608) {
        int n = idx & 127, kr = (idx >> 7) & 63, kc = (idx >> 13) & 3, nt = idx >> 15;
        float f = wqkv[(kc * 64 + kr) * 768 + nt * 128 + n];
        int o = ((nt * 4 + kc) * 64 + kr) * 136 + n;
        g_w1h[o] = __float2bfloat16(f);
        g_w1l[o] = __float2bfloat16(bres(f));
    } else {
        int t = idx - 196608;
        int n = t & 127, kr = (t >> 7) & 63, kc = (t >> 13) & 3, nt = t >> 15;
        float f = wout[(kc * 64 + kr) * 256 + nt * 128 + n];
        int o = ((nt * 4 + kc) * 64 + kr) * 136 + n;
        g_w2h[o] = __float2bfloat16(f);
        g_w2l[o] = __float2bfloat16(bres(f));
    }
}

// ======================= K1: QKV GEMM ======================================
// smem: AHI 0 (67584), ALO 67584, B ring 135168 (2 x 34816) -> 204800
#define K_ALO  67584
#define K_BB   135168
#define K1_SMEM 204800

__global__ __launch_bounds__(256, 1) void k1_qkv(const float* __restrict__ x) {
    extern __shared__ __align__(16) char sm[];
    const uint32_t sb = smem_u32(sm);
    const int tid = threadIdx.x, lane = tid & 31, wid = tid >> 5;
    const int wm = (wid & 1) * 64, wn = (wid >> 1) * 32;
    const int m0 = blockIdx.x * 128;

    stage_B(sb + K_BB, g_w1h, g_w1l, tid);     // prefetch chunk 0

    // stage A slab (transposed gather from x), hi/lo bf16
    for (int e = tid; e < 128 * 64; e += 256) {
        int row = e >> 6, k4 = (e & 63) << 2;
        int r = m0 + row, g = r / 5, l = r - g * 5, b = g / HW_, hw = g - b * HW_;
        const float4 v = *(const float4*)(x + ((size_t)((b * 5 + l) * HW_ + hw)) * 256 + k4);
        uint32_t off = (uint32_t)(row * AP + k4) * 2;
        *(uint64_t*)(sm + off) = pack4(v.x, v.y, v.z, v.w);
        *(uint64_t*)(sm + K_ALO + off) = pack4(bres(v.x), bres(v.y), bres(v.z), bres(v.w));
    }

    const uint32_t aoff = (uint32_t)(((wm + (lane & 15)) * AP + ((lane >> 4) << 3)) * 2);
    const uint32_t boff = (uint32_t)(((lane & 15) * BP + wn) * 2);

    float acc[4][4][4];
    for (int c = 0; c < 24; ++c) {             // chunk c = (nt = c/4, kc = c%4)
        const int kc = c & 3;
        if (kc == 0) {
            #pragma unroll
            for (int i = 0; i < 4; ++i)
                #pragma unroll
                for (int j = 0; j < 4; ++j)
                    #pragma unroll
                    for (int q = 0; q < 4; ++q) acc[i][j][q] = 0.f;
        }
        if (c > 0) __syncthreads();            // mma(c-1) complete -> buf free
        if (c + 1 < 24)
            stage_B(sb + K_BB + ((c + 1) & 1) * BUF_B,
                    g_w1h + (c + 1) * 8704, g_w1l + (c + 1) * 8704, tid);
        if (c + 1 < 24) { CP_WAIT(1); } else { CP_WAIT(0); }
        __syncthreads();                       // chunk c visible

        uint32_t bb = sb + K_BB + (c & 1) * BUF_B;
        mma_chunk(acc,
                  sb + aoff + (uint32_t)(kc * 64 * 2),
                  sb + K_ALO + aoff + (uint32_t)(kc * 64 * 2),
                  bb + boff, bb + CHUNK_B + boff);

        if (kc == 3) {
            const int nt = c >> 2;
            #pragma unroll
            for (int i = 0; i < 4; ++i) {
                int row = m0 + wm + i * 16 + (lane >> 2);
                #pragma unroll
                for (int j = 0; j < 4; ++j) {
                    int col = nt * 128 + wn + j * 8 + (lane & 3) * 2;
                    float* p = g_qkv + (size_t)row * 768 + col;
                    *(float2*)p = make_float2(acc[i][j][0], acc[i][j][1]);
                    *(float2*)(p + 8 * 768) = make_float2(acc[i][j][2], acc[i][j][3]);
                }
            }
        }
    }
}

// ======================= K23: fused attention + output GEMM ================
// A tile hi/lo at 0 / 67584 (as K1). qs/kk alias the ENTIRE B ring
// (135168..204800, 69632 B >= 2*135*33*4 = 35640 B). sc/ms/bias live past it.
// Chunk-0 prefetch happens AFTER the attention phase (qs/kk dead by then).
// Max groups per CTA: 128 rows spanning ceil((128+4)/5) = 27 groups, nr<=135.
#define F_SC    204800                 // 27*25 floats = 2700 B
#define F_MS    207552                 // 135 ints    = 540 B
#define F_BIAS  208128                 // 256 floats  = 1024 B
#define K23_SMEM 209152

__global__ __launch_bounds__(256, 1) void k23_attn_out(const int* __restrict__ mask,
                                                       const float* __restrict__ bout,
                                                       float* __restrict__ out) {
    extern __shared__ __align__(16) char sm[];
    const uint32_t sb = smem_u32(sm);
    const int tid = threadIdx.x, lane = tid & 31, wid = tid >> 5;
    const int wm = (wid & 1) * 64, wn = (wid >> 1) * 32;
    const int m0 = blockIdx.x * 128;
    const int gLo = m0 / 5;
    const int gHi = (m0 + 127) / 5;
    const int ng = gHi - gLo + 1;              // <= 27
    const int nr = ng * 5;                     // <= 135
    const int r0 = gLo * 5;

    float* qs  = (float*)(sm + K_BB);          // [135][33] max
    float* kk  = qs + 135 * 33;                // [135][33] max
    float* sc  = (float*)(sm + F_SC);          // [27][25]
    int*   ms  = (int*)(sm + F_MS);            // [135]
    float* bias = (float*)(sm + F_BIAS);

    for (int e = tid; e < nr; e += 256) ms[e] = mask[r0 + e];
    if (tid < 256) bias[tid] = bout[tid];

    const float scale = 0.17677669529663687f;

    // ---------------- attention: per head, write A tile hi/lo --------------
    for (int h = 0; h < 8; ++h) {
        for (int e = tid; e < nr * 64; e += 256) {       // load q,k rows
            int row = e >> 6, t = e & 63, sel = t >> 5, d = t & 31;
            float v = g_qkv[(size_t)(r0 + row) * 768 + sel * 256 + h * 32 + d];
            (sel ? kk : qs)[row * 33 + d] = v;
        }
        __syncthreads();
        for (int e = tid; e < ng * 25; e += 256) {       // masked scores
            int g = e / 25, rr = e % 25, i = rr / 5, j = rr % 5;
            float s;
            if (ms[g * 5 + j] == 0) s = -1e30f;
            else {
                const float* q = qs + (g * 5 + i) * 33;
                const float* k = kk + (g * 5 + j) * 33;
                s = 0.f;
                #pragma unroll
                for (int d = 0; d < 32; ++d) s = fmaf(q[d], k[d], s);
                s *= scale;
            }
            sc[e] = s;
        }
        __syncthreads();
        if (tid < nr) {                                  // softmax per (g,i)
            float* r = sc + (tid / 5) * 25 + (tid % 5) * 5;
            float mx = r[0];
            #pragma unroll
            for (int j = 1; j < 5; ++j) mx = fmaxf(mx, r[j]);
            float ev[5], s = 0.f;
            #pragma unroll
            for (int j = 0; j < 5; ++j) { ev[j] = __expf(r[j] - mx); s += ev[j]; }
            float inv = 1.f / s;
            #pragma unroll
            for (int j = 0; j < 5; ++j) r[j] = ev[j] * inv;
        }
        __syncthreads();
        for (int e = tid; e < 128 * 8; e += 256) {       // PV -> A tile bf16
            int row = e >> 3, dq = (e & 7) << 2;
            int rg = m0 + row, gg = rg / 5, i = rg - gg * 5;
            const float* p = sc + (gg - gLo) * 25 + i * 5;
            float4 o = make_float4(0.f, 0.f, 0.f, 0.f);
            #pragma unroll
            for (int j = 0; j < 5; ++j) {
                const float4 v = *(const float4*)(g_qkv + (size_t)(gg * 5 + j) * 768 + 512 + h * 32 + dq);
                o.x = fmaf(p[j], v.x, o.x); o.y = fmaf(p[j], v.y, o.y);
                o.z = fmaf(p[j], v.z, o.z); o.w = fmaf(p[j], v.w, o.w);
            }
            uint32_t off = (uint32_t)(row * AP + h * 32 + dq) * 2;
            *(uint64_t*)(sm + off) = pack4(o.x, o.y, o.z, o.w);
            *(uint64_t*)(sm + K_ALO + off) = pack4(bres(o.x), bres(o.y), bres(o.z), bres(o.w));
        }
        __syncthreads();                                 // qs/kk reused next head
    }

    // ---------------- output GEMM + bias + transposed store ----------------
    // qs/kk dead from here; the B ring takes over that space.
    stage_B(sb + K_BB, g_w2h, g_w2l, tid);               // chunk 0 -> buf0

    const uint32_t aoff = (uint32_t)(((wm + (lane & 15)) * AP + ((lane >> 4) << 3)) * 2);
    const uint32_t boff = (uint32_t)(((lane & 15) * BP + wn) * 2);

    float acc[4][4][4];
    for (int c = 0; c < 8; ++c) {
        const int kc = c & 3;
        if (kc == 0) {
            #pragma unroll
            for (int i = 0; i < 4; ++i)
                #pragma unroll
                for (int j = 0; j < 4; ++j)
                    #pragma unroll
                    for (int q = 0; q < 4; ++q) acc[i][j][q] = 0.f;
        }
        if (c > 0) __syncthreads();
        if (c + 1 < 8)
            stage_B(sb + K_BB + ((c + 1) & 1) * BUF_B,
                    g_w2h + (c + 1) * 8704, g_w2l + (c + 1) * 8704, tid);
        if (c + 1 < 8) { CP_WAIT(1); } else { CP_WAIT(0); }
        __syncthreads();

        uint32_t bb = sb + K_BB + (c & 1) * BUF_B;
        mma_chunk(acc,
                  sb + aoff + (uint32_t)(kc * 64 * 2),
                  sb + K_ALO + aoff + (uint32_t)(kc * 64 * 2),
                  bb + boff, bb + CHUNK_B + boff);

        if (kc == 3) {
            const int nt = c >> 2;
            #pragma unroll
            for (int i = 0; i < 4; ++i) {
                int r1 = m0 + wm + i * 16 + (lane >> 2);
                #pragma unroll
                for (int rr = 0; rr < 2; ++rr) {
                    int r = r1 + rr * 8;
                    int g = r / 5, l = r - g * 5, b = g / HW_, hw = g - b * HW_;
                    float* dst = out + ((size_t)((b * 5 + l) * HW_ + hw)) * 256;
                    #pragma unroll
                    for (int j = 0; j < 4; ++j) {
                        int col = nt * 128 + wn + j * 8 + (lane & 3) * 2;
                        float2 o = make_float2(acc[i][j][2 * rr] + bias[col],
                                               acc[i][j][2 * rr + 1] + bias[col + 1]);
                        *(float2*)(dst + col) = o;
                    }
                }
            }
        }
    }
}

// ===========================================================================
extern "C" void kernel_launch(void* const* d_in, const int* in_sizes, int n_in,
                              void* d_out, int out_size) {
    const float* x    = (const float*)d_in[0];
    const int*   mask = (const int*)d_in[1];
    const float* wqkv = (const float*)d_in[2];
    const float* wout = (const float*)d_in[3];
    const float* bout = (const float*)d_in[4];
    float*       out  = (float*)d_out;

    cudaFuncSetAttribute(k1_qkv, cudaFuncAttributeMaxDynamicSharedMemorySize, K1_SMEM);
    cudaFuncSetAttribute(k23_attn_out, cudaFuncAttributeMaxDynamicSharedMemorySize, K23_SMEM);

    prep_w<<<1024, 256>>>(wqkv, wout);
    k1_qkv<<<660, 256, K1_SMEM>>>(x);
    k23_attn_out<<<660, 256, K23_SMEM>>>(mask, bout, out);
}

// round 9
// speedup vs baseline: 1.1301x; 1.1301x over previous
#include <cuda_runtime.h>
#include <cuda_bf16.h>
#include <stdint.h>

// ===========================================================================
// CavAttention via mma.sync bf16 hi/lo split precision
// Round 9: Round-6 three-kernel structure + single-stage merged-pass MMA core
//   prep: wqkv/wout -> bf16 hi/lo global images (padded pitch 136)
//   K1:   qkv = xp @ wqkv                 (HMMA)  -> g_qkv
//   K2:   masked softmax + P@V            (SIMT)  -> g_att
//   K3:   out = att @ wout + bias         (HMMA, transposed store)
// ===========================================================================

#define HW_   8448
#define NROWS 84480

__device__ __align__(16) float g_qkv[(size_t)NROWS * 768];
__device__ __align__(16) float g_att[(size_t)NROWS * 256];
__device__ __align__(16) __nv_bfloat16 g_w1h[6 * 4 * 64 * 136];
__device__ __align__(16) __nv_bfloat16 g_w1l[6 * 4 * 64 * 136];
__device__ __align__(16) __nv_bfloat16 g_w2h[2 * 4 * 64 * 136];
__device__ __align__(16) __nv_bfloat16 g_w2l[2 * 4 * 64 * 136];

#define AP 264            // A smem pitch (bf16 elems): 528B ≡ 4 banks mod 32
#define BP 136            // B smem pitch: 272B ≡ 4 banks mod 32

#define CHUNK_B  17408                    // one 64x136 bf16 image (bytes)
#define BUF_B    (2 * CHUNK_B)            // hi + lo per chunk

// ----------------------------- helpers ------------------------------------
__device__ __forceinline__ uint32_t smem_u32(const void* p) {
    uint32_t a;
    asm("{ .reg .u64 t; cvta.to.shared.u64 t, %1; cvt.u32.u64 %0, t; }" : "=r"(a) : "l"(p));
    return a;
}
__device__ __forceinline__ float bres(float f) {
    return f - __bfloat162float(__float2bfloat16(f));
}
__device__ __forceinline__ uint64_t pack4(float a0, float a1, float a2, float a3) {
    uint64_t r = (uint64_t)__bfloat16_as_ushort(__float2bfloat16(a0));
    r |= (uint64_t)__bfloat16_as_ushort(__float2bfloat16(a1)) << 16;
    r |= (uint64_t)__bfloat16_as_ushort(__float2bfloat16(a2)) << 32;
    r |= (uint64_t)__bfloat16_as_ushort(__float2bfloat16(a3)) << 48;
    return r;
}
__device__ __forceinline__ void cpa16(uint32_t dst, const void* src) {
    asm volatile("cp.async.cg.shared.global [%0], [%1], 16;" :: "r"(dst), "l"(src));
}
#define CP_COMMIT() asm volatile("cp.async.commit_group;" ::: "memory")
#define CP_WAIT(n)  asm volatile("cp.async.wait_group %0;" :: "n"(n) : "memory")

__device__ __forceinline__ void ldmA(uint32_t* r, uint32_t addr) {
    asm volatile("ldmatrix.sync.aligned.m8n8.x4.shared.b16 {%0,%1,%2,%3}, [%4];"
                 : "=r"(r[0]), "=r"(r[1]), "=r"(r[2]), "=r"(r[3]) : "r"(addr));
}
__device__ __forceinline__ void ldmB(uint32_t* r, uint32_t addr) {
    asm volatile("ldmatrix.sync.aligned.m8n8.x2.trans.shared.b16 {%0,%1}, [%2];"
                 : "=r"(r[0]), "=r"(r[1]) : "r"(addr));
}
__device__ __forceinline__ void mma16816(float* c, const uint32_t* a, const uint32_t* b) {
    asm volatile("mma.sync.aligned.m16n8k16.row.col.f32.bf16.bf16.f32 "
                 "{%0,%1,%2,%3}, {%4,%5,%6,%7}, {%8,%9}, {%0,%1,%2,%3};"
                 : "+f"(c[0]), "+f"(c[1]), "+f"(c[2]), "+f"(c[3])
                 : "r"(a[0]), "r"(a[1]), "r"(a[2]), "r"(a[3]), "r"(b[0]), "r"(b[1]));
}

// single-stage merged-pass 64-deep K chunk. acc = warp tile 64x32.
// Per k16-step: 16 ldmatrix (each operand loaded ONCE) feeding 48 MMAs.
__device__ __forceinline__ void mma_chunk(float acc[4][4][4],
                                          uint32_t aHi, uint32_t aLo,
                                          uint32_t bHi, uint32_t bLo) {
    #pragma unroll
    for (int ks = 0; ks < 4; ++ks) {
        uint32_t ah[4][4], al[4][4], bh[4][2], bl[4][2];
        #pragma unroll
        for (int i = 0; i < 4; ++i) {
            ldmA(ah[i], aHi + (uint32_t)((i * 16 * AP + ks * 16) * 2));
            ldmA(al[i], aLo + (uint32_t)((i * 16 * AP + ks * 16) * 2));
        }
        #pragma unroll
        for (int j = 0; j < 4; ++j) {
            ldmB(bh[j], bHi + (uint32_t)((ks * 16 * BP + j * 8) * 2));
            ldmB(bl[j], bLo + (uint32_t)((ks * 16 * BP + j * 8) * 2));
        }
        #pragma unroll
        for (int i = 0; i < 4; ++i)
            #pragma unroll
            for (int j = 0; j < 4; ++j)
                mma16816(acc[i][j], ah[i], bh[j]);
        #pragma unroll
        for (int i = 0; i < 4; ++i)
            #pragma unroll
            for (int j = 0; j < 4; ++j)
                mma16816(acc[i][j], ah[i], bl[j]);
        #pragma unroll
        for (int i = 0; i < 4; ++i)
            #pragma unroll
            for (int j = 0; j < 4; ++j)
                mma16816(acc[i][j], al[i], bh[j]);
    }
}

// issue one B chunk (hi+lo) via cp.async; 1088 uint4 per image
__device__ __forceinline__ void stage_B(uint32_t dst, const __nv_bfloat16* srcH,
                                        const __nv_bfloat16* srcL, int tid) {
    const char* sH = (const char*)srcH;
    const char* sL = (const char*)srcL;
    #pragma unroll
    for (int q = 0; q < 5; ++q) {
        int e = tid + q * 256;
        if (e < 1088) {
            cpa16(dst + e * 16, sH + e * 16);
            cpa16(dst + CHUNK_B + e * 16, sL + e * 16);
        }
    }
    CP_COMMIT();
}

// ======================= prep: weight conversion ===========================
__global__ __launch_bounds__(256) void prep_w(const float* __restrict__ wqkv,
                                              const float* __restrict__ wout) {
    int idx = blockIdx.x * 256 + threadIdx.x;
    if (idx < 196608) {
        int n = idx & 127, kr = (idx >> 7) & 63, kc = (idx >> 13) & 3, nt = idx >> 15;
        float f = wqkv[(kc * 64 + kr) * 768 + nt * 128 + n];
        int o = ((nt * 4 + kc) * 64 + kr) * 136 + n;
        g_w1h[o] = __float2bfloat16(f);
        g_w1l[o] = __float2bfloat16(bres(f));
    } else {
        int t = idx - 196608;
        int n = t & 127, kr = (t >> 7) & 63, kc = (t >> 13) & 3, nt = t >> 15;
        float f = wout[(kc * 64 + kr) * 256 + nt * 128 + n];
        int o = ((nt * 4 + kc) * 64 + kr) * 136 + n;
        g_w2h[o] = __float2bfloat16(f);
        g_w2l[o] = __float2bfloat16(bres(f));
    }
}

// ======================= K1: QKV GEMM ======================================
// smem: AHI 0 (67584B), ALO 67584, B ring 135168 (2 x 34816) -> 204800
#define K_ALO  67584
#define K_BB   135168
#define K1_SMEM 204800

__global__ __launch_bounds__(256, 1) void k1_qkv(const float* __restrict__ x) {
    extern __shared__ __align__(16) char sm[];
    const uint32_t sb = smem_u32(sm);
    const int tid = threadIdx.x, lane = tid & 31, wid = tid >> 5;
    const int wm = (wid & 1) * 64, wn = (wid >> 1) * 32;
    const int m0 = blockIdx.x * 128;

    stage_B(sb + K_BB, g_w1h, g_w1l, tid);     // prefetch chunk 0

    // stage A slab (transposed gather from x), hi/lo bf16
    for (int e = tid; e < 128 * 64; e += 256) {
        int row = e >> 6, k4 = (e & 63) << 2;
        int r = m0 + row, g = r / 5, l = r - g * 5, b = g / HW_, hw = g - b * HW_;
        const float4 v = *(const float4*)(x + ((size_t)((b * 5 + l) * HW_ + hw)) * 256 + k4);
        uint32_t off = (uint32_t)(row * AP + k4) * 2;
        *(uint64_t*)(sm + off) = pack4(v.x, v.y, v.z, v.w);
        *(uint64_t*)(sm + K_ALO + off) = pack4(bres(v.x), bres(v.y), bres(v.z), bres(v.w));
    }

    const uint32_t aoff = (uint32_t)(((wm + (lane & 15)) * AP + ((lane >> 4) << 3)) * 2);
    const uint32_t boff = (uint32_t)(((lane & 15) * BP + wn) * 2);

    float acc[4][4][4];
    for (int c = 0; c < 24; ++c) {             // chunk c = (nt = c/4, kc = c%4)
        const int kc = c & 3;
        if (kc == 0) {
            #pragma unroll
            for (int i = 0; i < 4; ++i)
                #pragma unroll
                for (int j = 0; j < 4; ++j)
                    #pragma unroll
                    for (int q = 0; q < 4; ++q) acc[i][j][q] = 0.f;
        }
        if (c > 0) __syncthreads();            // mma(c-1) complete -> buf free
        if (c + 1 < 24)
            stage_B(sb + K_BB + ((c + 1) & 1) * BUF_B,
                    g_w1h + (c + 1) * 8704, g_w1l + (c + 1) * 8704, tid);
        if (c + 1 < 24) { CP_WAIT(1); } else { CP_WAIT(0); }
        __syncthreads();                       // chunk c visible

        uint32_t bb = sb + K_BB + (c & 1) * BUF_B;
        mma_chunk(acc,
                  sb + aoff + (uint32_t)(kc * 64 * 2),
                  sb + K_ALO + aoff + (uint32_t)(kc * 64 * 2),
                  bb + boff, bb + CHUNK_B + boff);

        if (kc == 3) {
            const int nt = c >> 2;
            #pragma unroll
            for (int i = 0; i < 4; ++i) {
                int row = m0 + wm + i * 16 + (lane >> 2);
                #pragma unroll
                for (int j = 0; j < 4; ++j) {
                    int col = nt * 128 + wn + j * 8 + (lane & 3) * 2;
                    float* p = g_qkv + (size_t)row * 768 + col;
                    *(float2*)p = make_float2(acc[i][j][0], acc[i][j][1]);
                    *(float2*)(p + 8 * 768) = make_float2(acc[i][j][2], acc[i][j][3]);
                }
            }
        }
    }
}

// ======================= K2: masked softmax attention (SIMT) ===============
#define K2_STR 769
#define K2_SMEM (20 * K2_STR * 4 + 100 * 4 + 20 * 4)

__global__ __launch_bounds__(128) void k2_attn(const int* __restrict__ mask) {
    extern __shared__ __align__(16) float sl[];           // [20][769]
    float* sc = sl + 20 * K2_STR;                         // [4][25]
    int*   ms = (int*)(sc + 100);                         // [20]
    const int tid = threadIdx.x;
    const int r0 = blockIdx.x * 20;
    const int g0 = blockIdx.x * 4;

    for (int e = tid; e < 20; e += 128) ms[e] = mask[g0 * 5 + e];
    for (int e = tid; e < 20 * 192; e += 128) {
        int row = e / 192, c4 = (e % 192) * 4;
        const float4 v = *(const float4*)(g_qkv + (size_t)(r0 + row) * 768 + c4);
        float* d = sl + row * K2_STR + c4;
        d[0] = v.x; d[1] = v.y; d[2] = v.z; d[3] = v.w;
    }
    __syncthreads();

    const float scale = 0.17677669529663687f;
    for (int h = 0; h < 8; ++h) {
        const int hc = h * 32;
        if (tid < 100) {
            int g = tid / 25, rr = tid % 25, i = rr / 5, j = rr % 5;
            float s;
            if (ms[g * 5 + j] == 0) s = -1e30f;
            else {
                const float* q = sl + (g * 5 + i) * K2_STR + hc;
                const float* k = sl + (g * 5 + j) * K2_STR + 256 + hc;
                s = 0.f;
                #pragma unroll
                for (int d = 0; d < 32; ++d) s = fmaf(q[d], k[d], s);
                s *= scale;
            }
            sc[tid] = s;
        }
        __syncthreads();
        if (tid < 20) {
            float* r = sc + (tid / 5) * 25 + (tid % 5) * 5;
            float mx = r[0];
            #pragma unroll
            for (int j = 1; j < 5; ++j) mx = fmaxf(mx, r[j]);
            float ev[5], s = 0.f;
            #pragma unroll
            for (int j = 0; j < 5; ++j) { ev[j] = __expf(r[j] - mx); s += ev[j]; }
            float inv = 1.f / s;
            #pragma unroll
            for (int j = 0; j < 5; ++j) r[j] = ev[j] * inv;
        }
        __syncthreads();
        for (int e = tid; e < 20 * 32; e += 128) {
            int row = e >> 5, d = e & 31;
            int g = row / 5, i = row - g * 5;
            const float* p = sc + g * 25 + i * 5;
            const float* v = sl + (g * 5) * K2_STR + 512 + hc + d;
            float o = 0.f;
            #pragma unroll
            for (int j = 0; j < 5; ++j) o = fmaf(p[j], v[j * K2_STR], o);
            g_att[(size_t)(r0 + row) * 256 + hc + d] = o;
        }
        __syncthreads();
    }
}

// ======================= K3: output GEMM + bias + transposed store =========
#define K3_BIAS 204800
#define K3_SMEM 205824

__global__ __launch_bounds__(256, 1) void k3_out(const float* __restrict__ bout,
                                                 float* __restrict__ out) {
    extern __shared__ __align__(16) char sm[];
    const uint32_t sb = smem_u32(sm);
    const int tid = threadIdx.x, lane = tid & 31, wid = tid >> 5;
    const int wm = (wid & 1) * 64, wn = (wid >> 1) * 32;
    const int m0 = blockIdx.x * 128;

    stage_B(sb + K_BB, g_w2h, g_w2l, tid);     // prefetch chunk 0

    if (tid < 256) ((float*)(sm + K3_BIAS))[tid] = bout[tid];

    for (int e = tid; e < 128 * 64; e += 256) {
        int row = e >> 6, k4 = (e & 63) << 2;
        const float4 v = *(const float4*)(g_att + (size_t)(m0 + row) * 256 + k4);
        uint32_t off = (uint32_t)(row * AP + k4) * 2;
        *(uint64_t*)(sm + off) = pack4(v.x, v.y, v.z, v.w);
        *(uint64_t*)(sm + K_ALO + off) = pack4(bres(v.x), bres(v.y), bres(v.z), bres(v.w));
    }

    const uint32_t aoff = (uint32_t)(((wm + (lane & 15)) * AP + ((lane >> 4) << 3)) * 2);
    const uint32_t boff = (uint32_t)(((lane & 15) * BP + wn) * 2);
    const float* bias = (const float*)(sm + K3_BIAS);

    float acc[4][4][4];
    for (int c = 0; c < 8; ++c) {
        const int kc = c & 3;
        if (kc == 0) {
            #pragma unroll
            for (int i = 0; i < 4; ++i)
                #pragma unroll
                for (int j = 0; j < 4; ++j)
                    #pragma unroll
                    for (int q = 0; q < 4; ++q) acc[i][j][q] = 0.f;
        }
        if (c > 0) __syncthreads();
        if (c + 1 < 8)
            stage_B(sb + K_BB + ((c + 1) & 1) * BUF_B,
                    g_w2h + (c + 1) * 8704, g_w2l + (c + 1) * 8704, tid);
        if (c + 1 < 8) { CP_WAIT(1); } else { CP_WAIT(0); }
        __syncthreads();

        uint32_t bb = sb + K_BB + (c & 1) * BUF_B;
        mma_chunk(acc,
                  sb + aoff + (uint32_t)(kc * 64 * 2),
                  sb + K_ALO + aoff + (uint32_t)(kc * 64 * 2),
                  bb + boff, bb + CHUNK_B + boff);

        if (kc == 3) {
            const int nt = c >> 2;
            #pragma unroll
            for (int i = 0; i < 4; ++i) {
                int r1 = m0 + wm + i * 16 + (lane >> 2);
                #pragma unroll
                for (int rr = 0; rr < 2; ++rr) {
                    int r = r1 + rr * 8;
                    int g = r / 5, l = r - g * 5, b = g / HW_, hw = g - b * HW_;
                    float* dst = out + ((size_t)((b * 5 + l) * HW_ + hw)) * 256;
                    #pragma unroll
                    for (int j = 0; j < 4; ++j) {
                        int col = nt * 128 + wn + j * 8 + (lane & 3) * 2;
                        float2 o = make_float2(acc[i][j][2 * rr] + bias[col],
                                               acc[i][j][2 * rr + 1] + bias[col + 1]);
                        *(float2*)(dst + col) = o;
                    }
                }
            }
        }
    }
}

// ===========================================================================
extern "C" void kernel_launch(void* const* d_in, const int* in_sizes, int n_in,
                              void* d_out, int out_size) {
    const float* x    = (const float*)d_in[0];
    const int*   mask = (const int*)d_in[1];
    const float* wqkv = (const float*)d_in[2];
    const float* wout = (const float*)d_in[3];
    const float* bout = (const float*)d_in[4];
    float*       out  = (float*)d_out;

    cudaFuncSetAttribute(k1_qkv, cudaFuncAttributeMaxDynamicSharedMemorySize, K1_SMEM);
    cudaFuncSetAttribute(k2_attn, cudaFuncAttributeMaxDynamicSharedMemorySize, K2_SMEM);
    cudaFuncSetAttribute(k3_out, cudaFuncAttributeMaxDynamicSharedMemorySize, K3_SMEM);

    prep_w<<<1024, 256>>>(wqkv, wout);
    k1_qkv<<<660, 256, K1_SMEM>>>(x);
    k2_attn<<<4224, 128, K2_SMEM>>>(mask);
    k3_out<<<660, 256, K3_SMEM>>>(bout, out);
}